// round 1
// baseline (speedup 1.0000x reference)
#include <cuda_runtime.h>
#include <cstdint>
#include <math.h>

// Problem constants
#define S_DIM 256
#define CH    32          // head dim
#define NH    8           // heads
#define CIN   128         // input channels
#define CQK   256         // NH*CH
#define NROWS (S_DIM * S_DIM)   // 65536 rows in flattened (s, l) space

// ---------------------------------------------------------------------------
// Scratch (device globals; allocation inside kernel_launch is forbidden)
// ---------------------------------------------------------------------------
__device__ float g_Q[(size_t)NROWS * CQK];
__device__ float g_K[(size_t)NROWS * CQK];
__device__ float g_V[(size_t)NROWS * CQK];
__device__ float g_G[(size_t)NROWS * CQK];
__device__ float g_O[(size_t)NROWS * CQK];
__device__ int   g_mask_code;   // 0=int32, 1=uint8, 2=float32

// ---------------------------------------------------------------------------
// Mask dtype detection (bool serialization is ambiguous: u8 / i32 / f32).
// Reads only n_elem bytes (safe lower bound for any of the three layouts).
//   - any byte >= 2            -> float32 (0x3F80.. pattern)
//   - any nonzero byte %4 != 0 -> uint8
//   - else                     -> int32
// ---------------------------------------------------------------------------
__global__ void detect_mask_kernel(const unsigned char* __restrict__ m, int nbytes)
{
    __shared__ int f_float, f_u8;
    if (threadIdx.x == 0) { f_float = 0; f_u8 = 0; }
    __syncthreads();
    int lf = 0, lu = 0;
    for (int i = threadIdx.x; i < nbytes; i += blockDim.x) {
        unsigned char v = m[i];
        if (v >= 2) lf = 1;
        if ((i & 3) && v) lu = 1;
    }
    if (lf) atomicOr(&f_float, 1);
    if (lu) atomicOr(&f_u8, 1);
    __syncthreads();
    if (threadIdx.x == 0)
        g_mask_code = f_float ? 2 : (f_u8 ? 1 : 0);
}

// ---------------------------------------------------------------------------
// Generic fp32 SGEMM, C[M,N] = A[M,K] @ B[K,N] with fused epilogue.
//   mode 0: none
//   mode 1: C *= scale                      (Q projection, 1/sqrt(C))
//   mode 2: C = sigmoid(C + evec[col])      (gate projection)
//   mode 3: C = C + evec[col]               (output projection, bo)
// BM=BN=64, BK=16, 256 threads, 4x4 microtile, float4 everywhere.
// All shapes here divide the tile sizes exactly, so no bounds checks.
// ---------------------------------------------------------------------------
#define BM 64
#define BN 64
#define BK 16

__global__ __launch_bounds__(256)
void sgemm_ep(const float* __restrict__ A, const float* __restrict__ B,
              float* __restrict__ C, int M, int N, int K,
              int mode, const float* __restrict__ evec, float scale)
{
    __shared__ float As[BK * BM];
    __shared__ float Bs[BK * BN];

    const int tid = threadIdx.x;
    const int bm  = blockIdx.y * BM;
    const int bn  = blockIdx.x * BN;

    // A tile loader: 64 rows x 16 k -> 1 float4/thread
    const int arow = tid >> 2;
    const int ak   = (tid & 3) * 4;
    // B tile loader: 16 rows x 64 cols -> 1 float4/thread
    const int brow = tid >> 4;
    const int bcol = (tid & 15) * 4;

    const int tx = tid & 15;   // col group (4 cols)
    const int ty = tid >> 4;   // row group (4 rows)

    float acc[4][4];
#pragma unroll
    for (int i = 0; i < 4; i++)
#pragma unroll
        for (int j = 0; j < 4; j++) acc[i][j] = 0.f;

    for (int k0 = 0; k0 < K; k0 += BK) {
        float4 av = *(const float4*)(A + (size_t)(bm + arow) * K + k0 + ak);
        As[(ak + 0) * BM + arow] = av.x;
        As[(ak + 1) * BM + arow] = av.y;
        As[(ak + 2) * BM + arow] = av.z;
        As[(ak + 3) * BM + arow] = av.w;
        *(float4*)&Bs[brow * BN + bcol] =
            *(const float4*)(B + (size_t)(k0 + brow) * N + bn + bcol);
        __syncthreads();

#pragma unroll
        for (int kk = 0; kk < BK; kk++) {
            float4 a4 = *(const float4*)&As[kk * BM + ty * 4];
            float4 b4 = *(const float4*)&Bs[kk * BN + tx * 4];
            float ar[4] = {a4.x, a4.y, a4.z, a4.w};
            float br[4] = {b4.x, b4.y, b4.z, b4.w};
#pragma unroll
            for (int i = 0; i < 4; i++)
#pragma unroll
                for (int j = 0; j < 4; j++)
                    acc[i][j] += ar[i] * br[j];
        }
        __syncthreads();
    }

#pragma unroll
    for (int i = 0; i < 4; i++) {
        const int row = bm + ty * 4 + i;
        float vals[4];
#pragma unroll
        for (int j = 0; j < 4; j++) {
            float z = acc[i][j];
            const int col = bn + tx * 4 + j;
            if (mode == 1)      z *= scale;
            else if (mode == 2) z = 1.f / (1.f + expf(-(z + evec[col])));
            else if (mode == 3) z += evec[col];
            vals[j] = z;
        }
        *(float4*)(C + (size_t)row * N + bn + tx * 4) =
            make_float4(vals[0], vals[1], vals[2], vals[3]);
    }
}

// ---------------------------------------------------------------------------
// Fused attention: per block = (head h, outer index s, q-half).
// 256 threads. smem: K tile (256x32), V tile (256x32), logits (128x257),
// mask-additive (256), row max/sum scratch.
// Phase 1: logits = bias + q.k/sqrt(C) + mask   (2 threads per q-row, k-split)
// Phase 2: row softmax (unnormalized p in smem, 1/l in regs)
// Phase 3: o = p @ V, fused * (1/l) * gate, store to g_O (c-split per thread)
// ---------------------------------------------------------------------------
#define LS_STRIDE 257
#define ATTN_SMEM ((256*32*2 + 128*LS_STRIDE + 256*3) * 4)

__global__ __launch_bounds__(256, 1)
void attn_kernel(const float* __restrict__ Q, const float* __restrict__ Km,
                 const float* __restrict__ V, const float* __restrict__ G,
                 const float* __restrict__ bias, const void* __restrict__ mask,
                 float* __restrict__ O)
{
    extern __shared__ float sm[];
    float* Ks   = sm;                    // 256*32
    float* Vs   = Ks + 256 * 32;         // 256*32
    float* Ls   = Vs + 256 * 32;         // 128*257
    float* addm = Ls + 128 * LS_STRIDE;  // 256
    float* msm  = addm + 256;            // 256 (2 per row)
    float* lsm  = msm + 256;             // 256

    const int h  = blockIdx.x;
    const int s  = blockIdx.y;
    const int qh = blockIdx.z;
    const int t  = threadIdx.x;
    const int code = g_mask_code;

    // ---- stage K/V tiles (rows s*256+k, cols h*32..h*32+31) ----
    {
        const float4* Kg4 = (const float4*)Km;
        const float4* Vg4 = (const float4*)V;
        const size_t rowbase = ((size_t)s * S_DIM) * (CQK / 4) + h * (CH / 4);
#pragma unroll
        for (int f = t; f < 256 * (CH / 4); f += 256) {
            int k = f >> 3, c4 = f & 7;
            ((float4*)Ks)[k * (CH / 4) + c4] = Kg4[rowbase + (size_t)k * (CQK / 4) + c4];
            ((float4*)Vs)[k * (CH / 4) + c4] = Vg4[rowbase + (size_t)k * (CQK / 4) + c4];
        }
    }
    // ---- mask -> additive ----
    {
        const int idx = s * S_DIM + t;
        bool mv;
        if (code == 2)      mv = ((const float*)mask)[idx] != 0.f;
        else if (code == 1) mv = ((const unsigned char*)mask)[idx] != 0;
        else                mv = ((const int*)mask)[idx] != 0;
        addm[t] = mv ? 0.f : -1e30f;
    }
    // ---- stage bias tile into Ls (rows qh*128.., all 256 k) ----
    {
        const float4* Bg4 = (const float4*)bias;
        const size_t bbase = ((size_t)(h * S_DIM + qh * 128)) * (S_DIM / 4);
#pragma unroll
        for (int f = t; f < 128 * (S_DIM / 4); f += 256) {
            int qi = f >> 6, k4 = f & 63;
            float4 b4 = Bg4[bbase + (size_t)qi * (S_DIM / 4) + k4];
            float* lp = &Ls[qi * LS_STRIDE + k4 * 4];
            lp[0] = b4.x; lp[1] = b4.y; lp[2] = b4.z; lp[3] = b4.w;
        }
    }
    __syncthreads();

    // ---- phase 1: logits. thread (q = t&127, kh = t>>7) covers 128 k ----
    const int q  = t & 127;
    const int kh = t >> 7;
    float* lrow = &Ls[q * LS_STRIDE];

    float qreg[CH];
    {
        const float4* qp = (const float4*)(Q + ((size_t)(s * S_DIM + qh * 128 + q)) * CQK + h * CH);
#pragma unroll
        for (int i = 0; i < 8; i++) {
            float4 v = qp[i];
            qreg[4 * i] = v.x; qreg[4 * i + 1] = v.y;
            qreg[4 * i + 2] = v.z; qreg[4 * i + 3] = v.w;
        }
    }
#pragma unroll 2
    for (int kk = 0; kk < 128; kk++) {
        const int k = kh * 128 + kk;
        const float4* kv = (const float4*)&Ks[k * CH];
        float d0 = 0.f, d1 = 0.f, d2 = 0.f, d3 = 0.f;
#pragma unroll
        for (int c = 0; c < 8; c++) {
            float4 k4 = kv[c];
            d0 += qreg[4 * c]     * k4.x;
            d1 += qreg[4 * c + 1] * k4.y;
            d2 += qreg[4 * c + 2] * k4.z;
            d3 += qreg[4 * c + 3] * k4.w;
        }
        lrow[k] += (d0 + d1) + (d2 + d3) + addm[k];
    }
    __syncthreads();

    // ---- phase 2: softmax over k (two threads cooperate per row) ----
    float mloc = -INFINITY;
#pragma unroll 4
    for (int kk = 0; kk < 128; kk++)
        mloc = fmaxf(mloc, lrow[kh * 128 + kk]);
    msm[q * 2 + kh] = mloc;
    __syncthreads();
    const float mrow = fmaxf(msm[q * 2], msm[q * 2 + 1]);
    float lloc = 0.f;
#pragma unroll 2
    for (int kk = 0; kk < 128; kk++) {
        float p = __expf(lrow[kh * 128 + kk] - mrow);
        lrow[kh * 128 + kk] = p;
        lloc += p;
    }
    lsm[q * 2 + kh] = lloc;
    __syncthreads();
    const float rinv = 1.f / (lsm[q * 2] + lsm[q * 2 + 1]);

    // ---- phase 3: o = p @ V (thread covers 16 channels), gate, store ----
    const int cg = kh;   // channel group: 0 -> c[0..15], 1 -> c[16..31]
    float acc[16];
#pragma unroll
    for (int j = 0; j < 16; j++) acc[j] = 0.f;

#pragma unroll 2
    for (int k = 0; k < 256; k++) {
        const float p = lrow[k];
        const float4* vv = (const float4*)&Vs[k * CH + cg * 16];
#pragma unroll
        for (int j = 0; j < 4; j++) {
            float4 v4 = vv[j];
            acc[4 * j]     += p * v4.x;
            acc[4 * j + 1] += p * v4.y;
            acc[4 * j + 2] += p * v4.z;
            acc[4 * j + 3] += p * v4.w;
        }
    }
    {
        const size_t row = (size_t)(s * S_DIM + qh * 128 + q);
        const float4* gp = (const float4*)(G + row * CQK + h * CH + cg * 16);
        float4*       op = (float4*)(O + row * CQK + h * CH + cg * 16);
#pragma unroll
        for (int j = 0; j < 4; j++) {
            float4 gv = gp[j];
            float4 ov;
            ov.x = acc[4 * j]     * rinv * gv.x;
            ov.y = acc[4 * j + 1] * rinv * gv.y;
            ov.z = acc[4 * j + 2] * rinv * gv.z;
            ov.w = acc[4 * j + 3] * rinv * gv.w;
            op[j] = ov;
        }
    }
}

// ---------------------------------------------------------------------------
// Launch
// ---------------------------------------------------------------------------
extern "C" void kernel_launch(void* const* d_in, const int* in_sizes, int n_in,
                              void* d_out, int out_size)
{
    const float* x    = (const float*)d_in[0];
    const float* bias = (const float*)d_in[1];
    const void*  mask = d_in[2];
    const float* Wq   = (const float*)d_in[3];
    const float* Wk   = (const float*)d_in[4];
    const float* Wv   = (const float*)d_in[5];
    const float* Wo   = (const float*)d_in[6];
    const float* bo   = (const float*)d_in[7];
    const float* Wg   = (const float*)d_in[8];
    const float* bg   = (const float*)d_in[9];
    float* out = (float*)d_out;

    void *pQ, *pK, *pV, *pG, *pO;
    cudaGetSymbolAddress(&pQ, g_Q);
    cudaGetSymbolAddress(&pK, g_K);
    cudaGetSymbolAddress(&pV, g_V);
    cudaGetSymbolAddress(&pG, g_G);
    cudaGetSymbolAddress(&pO, g_O);
    float* Qb = (float*)pQ; float* Kb = (float*)pK; float* Vb = (float*)pV;
    float* Gb = (float*)pG; float* Ob = (float*)pO;

    const float qscale = 0.17677669529663687f;   // 1/sqrt(32)

    dim3 gproj(CQK / BN, NROWS / BM);   // (4, 1024)
    sgemm_ep<<<gproj, 256>>>(x, Wq, Qb, NROWS, CQK, CIN, 1, nullptr, qscale);
    sgemm_ep<<<gproj, 256>>>(x, Wk, Kb, NROWS, CQK, CIN, 0, nullptr, 1.f);
    sgemm_ep<<<gproj, 256>>>(x, Wv, Vb, NROWS, CQK, CIN, 0, nullptr, 1.f);
    sgemm_ep<<<gproj, 256>>>(x, Wg, Gb, NROWS, CQK, CIN, 2, bg, 1.f);

    detect_mask_kernel<<<1, 256>>>((const unsigned char*)mask, S_DIM * S_DIM);

    cudaFuncSetAttribute(attn_kernel, cudaFuncAttributeMaxDynamicSharedMemorySize, ATTN_SMEM);
    attn_kernel<<<dim3(NH, S_DIM, 2), 256, ATTN_SMEM>>>(Qb, Kb, Vb, Gb, bias, mask, Ob);

    dim3 gout(CIN / BN, NROWS / BM);    // (2, 1024)
    sgemm_ep<<<gout, 256>>>(Ob, Wo, out, NROWS, CIN, CQK, 3, bo, 1.f);
}

// round 2
// speedup vs baseline: 1.9400x; 1.9400x over previous
#include <cuda_runtime.h>
#include <cstdint>
#include <math.h>

// Problem constants
#define S_DIM 256
#define CH    32          // head dim
#define NH    8           // heads
#define CIN   128         // input channels
#define CQK   256         // NH*CH
#define NROWS (S_DIM * S_DIM)   // 65536 rows in flattened (s, l) space

// ---------------------------------------------------------------------------
// Scratch (device globals; allocation inside kernel_launch is forbidden)
// ---------------------------------------------------------------------------
__device__ float g_Q[(size_t)NROWS * CQK];
__device__ float g_K[(size_t)NROWS * CQK];
__device__ float g_V[(size_t)NROWS * CQK];
__device__ float g_G[(size_t)NROWS * CQK];
__device__ float g_O[(size_t)NROWS * CQK];
__device__ int   g_mask_code;   // 0=int32, 1=uint8, 2=float32

// ---------------------------------------------------------------------------
// Mask dtype detection (bool serialization ambiguous: u8 / i32 / f32).
// ---------------------------------------------------------------------------
__global__ void detect_mask_kernel(const unsigned char* __restrict__ m, int nbytes)
{
    __shared__ int f_float, f_u8;
    if (threadIdx.x == 0) { f_float = 0; f_u8 = 0; }
    __syncthreads();
    int lf = 0, lu = 0;
    for (int i = threadIdx.x; i < nbytes; i += blockDim.x) {
        unsigned char v = m[i];
        if (v >= 2) lf = 1;
        if ((i & 3) && v) lu = 1;
    }
    if (lf) atomicOr(&f_float, 1);
    if (lu) atomicOr(&f_u8, 1);
    __syncthreads();
    if (threadIdx.x == 0)
        g_mask_code = f_float ? 2 : (f_u8 ? 1 : 0);
}

// ---------------------------------------------------------------------------
// fp32 SGEMM v2: 128x128 tile, BK=8, 256 threads, 8x8 microtile.
//   mode 0: none
//   mode 1: C *= scale                      (Q projection, 1/sqrt(C))
//   mode 2: C = sigmoid(C + evec[col])      (gate projection)
//   mode 3: C = C + evec[col]               (output projection, bo)
// All shapes divide tile sizes exactly (M=65536, N in {256,128}, K in {128,256}).
// ---------------------------------------------------------------------------
#define GBM 128
#define GBN 128
#define GBK 8

__global__ __launch_bounds__(256)
void sgemm2(const float* __restrict__ A, const float* __restrict__ B,
            float* __restrict__ C, int M, int N, int K,
            int mode, const float* __restrict__ evec, float scale)
{
    __shared__ float As[GBK * GBM];   // [k][m] (transposed A tile)
    __shared__ float Bs[GBK * GBN];   // [k][n]

    const int t  = threadIdx.x;
    const int bm = blockIdx.y * GBM;
    const int bn = blockIdx.x * GBN;

    // A loader: 128 rows x 8 k; 2 threads per row -> 1 float4 each
    const int arow = t >> 1;
    const int ak   = (t & 1) * 4;
    // B loader: 8 rows x 128 cols -> 1 float4/thread
    const int brow = t >> 5;
    const int bcol = (t & 31) * 4;

    const int tx = t & 15;    // 8 output cols at tx*8
    const int ty = t >> 4;    // 8 output rows at ty*8

    float acc[8][8];
#pragma unroll
    for (int i = 0; i < 8; i++)
#pragma unroll
        for (int j = 0; j < 8; j++) acc[i][j] = 0.f;

    for (int k0 = 0; k0 < K; k0 += GBK) {
        float4 av = *(const float4*)(A + (size_t)(bm + arow) * K + k0 + ak);
        As[(ak + 0) * GBM + arow] = av.x;
        As[(ak + 1) * GBM + arow] = av.y;
        As[(ak + 2) * GBM + arow] = av.z;
        As[(ak + 3) * GBM + arow] = av.w;
        *(float4*)&Bs[brow * GBN + bcol] =
            *(const float4*)(B + (size_t)(k0 + brow) * N + bn + bcol);
        __syncthreads();

#pragma unroll
        for (int kk = 0; kk < GBK; kk++) {
            float4 a0 = *(const float4*)&As[kk * GBM + ty * 8];
            float4 a1 = *(const float4*)&As[kk * GBM + ty * 8 + 4];
            float4 b0 = *(const float4*)&Bs[kk * GBN + tx * 8];
            float4 b1 = *(const float4*)&Bs[kk * GBN + tx * 8 + 4];
            float ar[8] = {a0.x, a0.y, a0.z, a0.w, a1.x, a1.y, a1.z, a1.w};
            float br[8] = {b0.x, b0.y, b0.z, b0.w, b1.x, b1.y, b1.z, b1.w};
#pragma unroll
            for (int i = 0; i < 8; i++)
#pragma unroll
                for (int j = 0; j < 8; j++)
                    acc[i][j] += ar[i] * br[j];
        }
        __syncthreads();
    }

#pragma unroll
    for (int i = 0; i < 8; i++) {
        const int row = bm + ty * 8 + i;
        float vals[8];
#pragma unroll
        for (int j = 0; j < 8; j++) {
            float z = acc[i][j];
            const int col = bn + tx * 8 + j;
            if (mode == 1)      z *= scale;
            else if (mode == 2) z = 1.f / (1.f + expf(-(z + evec[col])));
            else if (mode == 3) z += evec[col];
            vals[j] = z;
        }
        *(float4*)(C + (size_t)row * N + bn + tx * 8) =
            make_float4(vals[0], vals[1], vals[2], vals[3]);
        *(float4*)(C + (size_t)row * N + bn + tx * 8 + 4) =
            make_float4(vals[4], vals[5], vals[6], vals[7]);
    }
}

// ---------------------------------------------------------------------------
// Flash-style fused attention. Block = (head h, outer index s), 256 threads,
// one thread per q-row. Online softmax fully in registers; K/V tiles in smem
// (all per-k loads are warp-uniform broadcasts). Gating fused in epilogue.
// smem = 64KB (K+V) + 1KB -> 2+ CTAs/SM, no phase barriers after staging.
// ---------------------------------------------------------------------------
__global__ __launch_bounds__(256, 2)
void attn_kernel(const float* __restrict__ Q, const float* __restrict__ Km,
                 const float* __restrict__ V, const float* __restrict__ G,
                 const float* __restrict__ bias, const void* __restrict__ mask,
                 float* __restrict__ O)
{
    __shared__ float Ks[S_DIM * CH];
    __shared__ float Vs[S_DIM * CH];
    __shared__ float addm[S_DIM];

    const int h = blockIdx.x;
    const int s = blockIdx.y;
    const int t = threadIdx.x;    // q row

    // ---- stage K/V tiles (rows s*256+k, cols h*32..h*32+31) ----
    {
        const float4* Kg4 = (const float4*)Km;
        const float4* Vg4 = (const float4*)V;
        const size_t rowbase = ((size_t)s * S_DIM) * (CQK / 4) + h * (CH / 4);
#pragma unroll
        for (int f = t; f < S_DIM * (CH / 4); f += 256) {
            int k = f >> 3, c4 = f & 7;
            ((float4*)Ks)[k * (CH / 4) + c4] = Kg4[rowbase + (size_t)k * (CQK / 4) + c4];
            ((float4*)Vs)[k * (CH / 4) + c4] = Vg4[rowbase + (size_t)k * (CQK / 4) + c4];
        }
    }
    // ---- mask -> additive ----
    {
        const int idx = s * S_DIM + t;
        const int code = g_mask_code;
        bool mv;
        if (code == 2)      mv = ((const float*)mask)[idx] != 0.f;
        else if (code == 1) mv = ((const unsigned char*)mask)[idx] != 0;
        else                mv = ((const int*)mask)[idx] != 0;
        addm[t] = mv ? 0.f : -1e30f;
    }
    __syncthreads();

    // ---- load this thread's q row (already scaled by 1/sqrt(C)) ----
    float qreg[CH];
    {
        const float4* qp = (const float4*)(Q + ((size_t)(s * S_DIM + t)) * CQK + h * CH);
#pragma unroll
        for (int i = 0; i < 8; i++) {
            float4 v = qp[i];
            qreg[4 * i] = v.x; qreg[4 * i + 1] = v.y;
            qreg[4 * i + 2] = v.z; qreg[4 * i + 3] = v.w;
        }
    }
    const float4* brow4 = (const float4*)(bias + ((size_t)(h * S_DIM + t)) * S_DIM);

    float m = -INFINITY, lsum = 0.f;
    float acc[CH];
#pragma unroll
    for (int c = 0; c < CH; c++) acc[c] = 0.f;

    for (int k0 = 0; k0 < S_DIM; k0 += 4) {
        float4 b4 = brow4[k0 >> 2];
        float bv[4] = {b4.x, b4.y, b4.z, b4.w};
#pragma unroll
        for (int j = 0; j < 4; j++) {
            const int k = k0 + j;
            const float4* kv = (const float4*)&Ks[k * CH];
            float d0 = 0.f, d1 = 0.f, d2 = 0.f, d3 = 0.f;
#pragma unroll
            for (int c = 0; c < 8; c++) {
                float4 k4 = kv[c];
                d0 += qreg[4 * c]     * k4.x;
                d1 += qreg[4 * c + 1] * k4.y;
                d2 += qreg[4 * c + 2] * k4.z;
                d3 += qreg[4 * c + 3] * k4.w;
            }
            const float logit = (d0 + d1) + (d2 + d3) + bv[j] + addm[k];

            const float mnew = fmaxf(m, logit);
            const float p = __expf(logit - mnew);
            if (mnew > m) {
                const float sc = __expf(m - mnew);
                lsum *= sc;
#pragma unroll
                for (int c = 0; c < CH; c++) acc[c] *= sc;
            }
            m = mnew;
            lsum += p;

            const float4* vv = (const float4*)&Vs[k * CH];
#pragma unroll
            for (int c = 0; c < 8; c++) {
                float4 v4 = vv[c];
                acc[4 * c]     += p * v4.x;
                acc[4 * c + 1] += p * v4.y;
                acc[4 * c + 2] += p * v4.z;
                acc[4 * c + 3] += p * v4.w;
            }
        }
    }

    // ---- epilogue: normalize, gate, store ----
    {
        const float rinv = 1.f / lsum;
        const size_t row = (size_t)(s * S_DIM + t);
        const float4* gp = (const float4*)(G + row * CQK + h * CH);
        float4*       op = (float4*)(O + row * CQK + h * CH);
#pragma unroll
        for (int i = 0; i < 8; i++) {
            float4 gv = gp[i];
            float4 ov;
            ov.x = acc[4 * i]     * rinv * gv.x;
            ov.y = acc[4 * i + 1] * rinv * gv.y;
            ov.z = acc[4 * i + 2] * rinv * gv.z;
            ov.w = acc[4 * i + 3] * rinv * gv.w;
            op[i] = ov;
        }
    }
}

// ---------------------------------------------------------------------------
// Launch
// ---------------------------------------------------------------------------
extern "C" void kernel_launch(void* const* d_in, const int* in_sizes, int n_in,
                              void* d_out, int out_size)
{
    const float* x    = (const float*)d_in[0];
    const float* bias = (const float*)d_in[1];
    const void*  mask = d_in[2];
    const float* Wq   = (const float*)d_in[3];
    const float* Wk   = (const float*)d_in[4];
    const float* Wv   = (const float*)d_in[5];
    const float* Wo   = (const float*)d_in[6];
    const float* bo   = (const float*)d_in[7];
    const float* Wg   = (const float*)d_in[8];
    const float* bg   = (const float*)d_in[9];
    float* out = (float*)d_out;

    void *pQ, *pK, *pV, *pG, *pO;
    cudaGetSymbolAddress(&pQ, g_Q);
    cudaGetSymbolAddress(&pK, g_K);
    cudaGetSymbolAddress(&pV, g_V);
    cudaGetSymbolAddress(&pG, g_G);
    cudaGetSymbolAddress(&pO, g_O);
    float* Qb = (float*)pQ; float* Kb = (float*)pK; float* Vb = (float*)pV;
    float* Gb = (float*)pG; float* Ob = (float*)pO;

    const float qscale = 0.17677669529663687f;   // 1/sqrt(32)

    dim3 gproj(CQK / GBN, NROWS / GBM);   // (2, 512)
    sgemm2<<<gproj, 256>>>(x, Wq, Qb, NROWS, CQK, CIN, 1, nullptr, qscale);
    sgemm2<<<gproj, 256>>>(x, Wk, Kb, NROWS, CQK, CIN, 0, nullptr, 1.f);
    sgemm2<<<gproj, 256>>>(x, Wv, Vb, NROWS, CQK, CIN, 0, nullptr, 1.f);
    sgemm2<<<gproj, 256>>>(x, Wg, Gb, NROWS, CQK, CIN, 2, bg, 1.f);

    detect_mask_kernel<<<1, 256>>>((const unsigned char*)mask, S_DIM * S_DIM);

    attn_kernel<<<dim3(NH, S_DIM), 256>>>(Qb, Kb, Vb, Gb, bias, mask, Ob);

    dim3 gout(CIN / GBN, NROWS / GBM);    // (1, 512)
    sgemm2<<<gout, 256>>>(Ob, Wo, out, NROWS, CIN, CQK, 3, bo, 1.f);
}

// round 3
// speedup vs baseline: 2.0848x; 1.0746x over previous
#include <cuda_runtime.h>
#include <cstdint>
#include <math.h>

// Problem constants
#define S_DIM 256
#define CH    32          // head dim
#define NH    8           // heads
#define CIN   128         // input channels
#define CQK   256         // NH*CH
#define NROWS (S_DIM * S_DIM)   // 65536 rows in flattened (s, l) space

typedef unsigned long long ull;

// ---------------------------------------------------------------------------
// Packed f32x2 helpers (sm_103a FFMA2 path — PTX-only)
// ---------------------------------------------------------------------------
__device__ __forceinline__ ull pk2(float lo, float hi) {
    ull r; asm("mov.b64 %0, {%1, %2};" : "=l"(r) : "f"(lo), "f"(hi)); return r;
}
__device__ __forceinline__ float2 upk2(ull v) {
    float lo, hi; asm("mov.b64 {%0, %1}, %2;" : "=f"(lo), "=f"(hi) : "l"(v));
    return make_float2(lo, hi);
}
__device__ __forceinline__ ull fma2(ull a, ull b, ull c) {
    ull d; asm("fma.rn.f32x2 %0, %1, %2, %3;" : "=l"(d) : "l"(a), "l"(b), "l"(c));
    return d;
}
__device__ __forceinline__ ull add2(ull a, ull b) {
    ull d; asm("add.rn.f32x2 %0, %1, %2;" : "=l"(d) : "l"(a), "l"(b));
    return d;
}
__device__ __forceinline__ ull mul2(ull a, ull b) {
    ull d; asm("mul.rn.f32x2 %0, %1, %2;" : "=l"(d) : "l"(a), "l"(b));
    return d;
}

// ---------------------------------------------------------------------------
// Scratch (device globals; allocation inside kernel_launch is forbidden)
// ---------------------------------------------------------------------------
__device__ float g_Q[(size_t)NROWS * CQK];
__device__ float g_K[(size_t)NROWS * CQK];
__device__ float g_V[(size_t)NROWS * CQK];
__device__ float g_G[(size_t)NROWS * CQK];
__device__ float g_O[(size_t)NROWS * CQK];
__device__ int   g_mask_code;   // 0=int32, 1=uint8, 2=float32

// ---------------------------------------------------------------------------
// Mask dtype detection (bool serialization ambiguous: u8 / i32 / f32).
// ---------------------------------------------------------------------------
__global__ void detect_mask_kernel(const unsigned char* __restrict__ m, int nbytes)
{
    __shared__ int f_float, f_u8;
    if (threadIdx.x == 0) { f_float = 0; f_u8 = 0; }
    __syncthreads();
    int lf = 0, lu = 0;
    for (int i = threadIdx.x; i < nbytes; i += blockDim.x) {
        unsigned char v = m[i];
        if (v >= 2) lf = 1;
        if ((i & 3) && v) lu = 1;
    }
    if (lf) atomicOr(&f_float, 1);
    if (lu) atomicOr(&f_u8, 1);
    __syncthreads();
    if (threadIdx.x == 0)
        g_mask_code = f_float ? 2 : (f_u8 ? 1 : 0);
}

// ---------------------------------------------------------------------------
// fp32 SGEMM v3: 128x128 tile, BK=8, 256 threads, 8x8 microtile via FFMA2,
// double-buffered smem (one sync per k-tile), global prefetch into registers.
//   mode 0: none / 1: C*=scale / 2: sigmoid(C+evec) / 3: C+evec
// ---------------------------------------------------------------------------
#define GBM 128
#define GBN 128
#define GBK 8

__global__ __launch_bounds__(256, 2)
void sgemm3(const float* __restrict__ A, const float* __restrict__ B,
            float* __restrict__ C, int M, int N, int K,
            int mode, const float* __restrict__ evec, float scale)
{
    __shared__ float As[2][GBK * GBM];   // [k][m] (transposed A tile)
    __shared__ float Bs[2][GBK * GBN];   // [k][n]

    const int t  = threadIdx.x;
    const int bm = blockIdx.y * GBM;
    const int bn = blockIdx.x * GBN;

    // A loader: 128 rows x 8 k; 2 threads per row -> 1 float4 each
    const int arow = t >> 1;
    const int ak   = (t & 1) * 4;
    // B loader: 8 rows x 128 cols -> 1 float4/thread
    const int brow = t >> 5;
    const int bcol = (t & 31) * 4;

    const int tx = t & 15;    // 8 output cols at tx*8
    const int ty = t >> 4;    // 8 output rows at ty*8

    ull acc2[8][4];
#pragma unroll
    for (int i = 0; i < 8; i++)
#pragma unroll
        for (int j = 0; j < 4; j++) acc2[i][j] = 0ULL;

    // prologue: stage tile 0 into buffer 0
    {
        float4 av = *(const float4*)(A + (size_t)(bm + arow) * K + ak);
        As[0][(ak + 0) * GBM + arow] = av.x;
        As[0][(ak + 1) * GBM + arow] = av.y;
        As[0][(ak + 2) * GBM + arow] = av.z;
        As[0][(ak + 3) * GBM + arow] = av.w;
        *(float4*)&Bs[0][brow * GBN + bcol] =
            *(const float4*)(B + (size_t)brow * N + bn + bcol);
    }
    __syncthreads();

    int p = 0;
    for (int k0 = 0; k0 < K; k0 += GBK) {
        const bool has_next = (k0 + GBK) < K;
        float4 av, bv;
        if (has_next) {
            av = *(const float4*)(A + (size_t)(bm + arow) * K + k0 + GBK + ak);
            bv = *(const float4*)(B + (size_t)(k0 + GBK + brow) * N + bn + bcol);
        }

        const float* Asp = As[p];
        const float* Bsp = Bs[p];
#pragma unroll
        for (int kk = 0; kk < GBK; kk++) {
            float4 a0 = *(const float4*)&Asp[kk * GBM + ty * 8];
            float4 a1 = *(const float4*)&Asp[kk * GBM + ty * 8 + 4];
            ulonglong2 b01 = *(const ulonglong2*)&Bsp[kk * GBN + tx * 8];
            ulonglong2 b23 = *(const ulonglong2*)&Bsp[kk * GBN + tx * 8 + 4];
            ull b2[4] = {b01.x, b01.y, b23.x, b23.y};
            ull aa[8] = {pk2(a0.x, a0.x), pk2(a0.y, a0.y), pk2(a0.z, a0.z), pk2(a0.w, a0.w),
                         pk2(a1.x, a1.x), pk2(a1.y, a1.y), pk2(a1.z, a1.z), pk2(a1.w, a1.w)};
#pragma unroll
            for (int i = 0; i < 8; i++)
#pragma unroll
                for (int j = 0; j < 4; j++)
                    acc2[i][j] = fma2(aa[i], b2[j], acc2[i][j]);
        }

        if (has_next) {
            const int q = p ^ 1;
            As[q][(ak + 0) * GBM + arow] = av.x;
            As[q][(ak + 1) * GBM + arow] = av.y;
            As[q][(ak + 2) * GBM + arow] = av.z;
            As[q][(ak + 3) * GBM + arow] = av.w;
            *(float4*)&Bs[q][brow * GBN + bcol] = bv;
            __syncthreads();
            p = q;
        }
    }

#pragma unroll
    for (int i = 0; i < 8; i++) {
        const int row = bm + ty * 8 + i;
        float vals[8];
#pragma unroll
        for (int j = 0; j < 4; j++) {
            float2 v = upk2(acc2[i][j]);
            vals[2 * j] = v.x; vals[2 * j + 1] = v.y;
        }
#pragma unroll
        for (int j = 0; j < 8; j++) {
            float z = vals[j];
            const int col = bn + tx * 8 + j;
            if (mode == 1)      z *= scale;
            else if (mode == 2) z = 1.f / (1.f + __expf(-(z + evec[col])));
            else if (mode == 3) z += evec[col];
            vals[j] = z;
        }
        *(float4*)(C + (size_t)row * N + bn + tx * 8) =
            make_float4(vals[0], vals[1], vals[2], vals[3]);
        *(float4*)(C + (size_t)row * N + bn + tx * 8 + 4) =
            make_float4(vals[4], vals[5], vals[6], vals[7]);
    }
}

// ---------------------------------------------------------------------------
// Flash-style fused attention v2 (FFMA2). Block = (head h, outer index s),
// 256 threads, one thread per q-row. Online softmax with 8-k chunks and a
// single guarded rescale per chunk. K/V in smem (warp-uniform broadcasts).
// ---------------------------------------------------------------------------
__global__ __launch_bounds__(256, 2)
void attn_kernel(const float* __restrict__ Q, const float* __restrict__ Km,
                 const float* __restrict__ V, const float* __restrict__ G,
                 const float* __restrict__ bias, const void* __restrict__ mask,
                 float* __restrict__ O)
{
    __shared__ float Ks[S_DIM * CH];
    __shared__ float Vs[S_DIM * CH];
    __shared__ float addm[S_DIM];

    const int h = blockIdx.x;
    const int s = blockIdx.y;
    const int t = threadIdx.x;    // q row

    // ---- stage K/V tiles (rows s*256+k, cols h*32..h*32+31) ----
    {
        const float4* Kg4 = (const float4*)Km;
        const float4* Vg4 = (const float4*)V;
        const size_t rowbase = ((size_t)s * S_DIM) * (CQK / 4) + h * (CH / 4);
#pragma unroll
        for (int f = t; f < S_DIM * (CH / 4); f += 256) {
            int k = f >> 3, c4 = f & 7;
            ((float4*)Ks)[k * (CH / 4) + c4] = Kg4[rowbase + (size_t)k * (CQK / 4) + c4];
            ((float4*)Vs)[k * (CH / 4) + c4] = Vg4[rowbase + (size_t)k * (CQK / 4) + c4];
        }
    }
    // ---- mask -> additive ----
    {
        const int idx = s * S_DIM + t;
        const int code = g_mask_code;
        bool mv;
        if (code == 2)      mv = ((const float*)mask)[idx] != 0.f;
        else if (code == 1) mv = ((const unsigned char*)mask)[idx] != 0;
        else                mv = ((const int*)mask)[idx] != 0;
        addm[t] = mv ? 0.f : -1e30f;
    }
    __syncthreads();

    // ---- load + pack this thread's q row (already scaled by 1/sqrt(C)) ----
    ull q2[16];
    {
        const float4* qp = (const float4*)(Q + ((size_t)(s * S_DIM + t)) * CQK + h * CH);
#pragma unroll
        for (int i = 0; i < 8; i++) {
            float4 v = qp[i];
            q2[2 * i]     = pk2(v.x, v.y);
            q2[2 * i + 1] = pk2(v.z, v.w);
        }
    }
    const float4* brow4 = (const float4*)(bias + ((size_t)(h * S_DIM + t)) * S_DIM);

    float m = -INFINITY, lsum = 0.f;
    ull acc2[16];
#pragma unroll
    for (int c = 0; c < 16; c++) acc2[c] = 0ULL;

    for (int k0 = 0; k0 < S_DIM; k0 += 8) {
        // -- 8 logits --
        float lg[8];
        float4 b4a = brow4[(k0 >> 2)];
        float4 b4b = brow4[(k0 >> 2) + 1];
        float bv[8] = {b4a.x, b4a.y, b4a.z, b4a.w, b4b.x, b4b.y, b4b.z, b4b.w};
#pragma unroll
        for (int j = 0; j < 8; j++) {
            const int k = k0 + j;
            const ulonglong2* kp = (const ulonglong2*)&Ks[k * CH];
            ull d0 = 0ULL, d1 = 0ULL, d2 = 0ULL, d3 = 0ULL;
#pragma unroll
            for (int c = 0; c < 4; c++) {
                ulonglong2 ka = kp[2 * c];
                ulonglong2 kb = kp[2 * c + 1];
                d0 = fma2(q2[4 * c],     ka.x, d0);
                d1 = fma2(q2[4 * c + 1], ka.y, d1);
                d2 = fma2(q2[4 * c + 2], kb.x, d2);
                d3 = fma2(q2[4 * c + 3], kb.y, d3);
            }
            float2 ds = upk2(add2(add2(d0, d1), add2(d2, d3)));
            lg[j] = ds.x + ds.y + bv[j] + addm[k];
        }
        // -- chunk max / guarded rescale --
        float bmax = lg[0];
#pragma unroll
        for (int j = 1; j < 8; j++) bmax = fmaxf(bmax, lg[j]);
        if (bmax > m) {
            const float sc = __expf(m - bmax);   // m=-inf first time -> 0
            lsum *= sc;
            const ull sc2 = pk2(sc, sc);
#pragma unroll
            for (int c = 0; c < 16; c++) acc2[c] = mul2(acc2[c], sc2);
            m = bmax;
        }
        // -- exp + AV --
#pragma unroll
        for (int j = 0; j < 8; j++) {
            const int k = k0 + j;
            const float pexp = __expf(lg[j] - m);
            lsum += pexp;
            const ull p2 = pk2(pexp, pexp);
            const ulonglong2* vp = (const ulonglong2*)&Vs[k * CH];
#pragma unroll
            for (int c = 0; c < 8; c++) {
                ulonglong2 v2l = vp[c];
                acc2[2 * c]     = fma2(p2, v2l.x, acc2[2 * c]);
                acc2[2 * c + 1] = fma2(p2, v2l.y, acc2[2 * c + 1]);
            }
        }
    }

    // ---- epilogue: normalize, gate, store ----
    {
        const float rinv = 1.f / lsum;
        const size_t row = (size_t)(s * S_DIM + t);
        const float4* gp = (const float4*)(G + row * CQK + h * CH);
        float4*       op = (float4*)(O + row * CQK + h * CH);
#pragma unroll
        for (int i = 0; i < 8; i++) {
            float4 gv = gp[i];
            float2 a0 = upk2(acc2[2 * i]);
            float2 a1 = upk2(acc2[2 * i + 1]);
            float4 ov;
            ov.x = a0.x * rinv * gv.x;
            ov.y = a0.y * rinv * gv.y;
            ov.z = a1.x * rinv * gv.z;
            ov.w = a1.y * rinv * gv.w;
            op[i] = ov;
        }
    }
}

// ---------------------------------------------------------------------------
// Launch
// ---------------------------------------------------------------------------
extern "C" void kernel_launch(void* const* d_in, const int* in_sizes, int n_in,
                              void* d_out, int out_size)
{
    const float* x    = (const float*)d_in[0];
    const float* bias = (const float*)d_in[1];
    const void*  mask = d_in[2];
    const float* Wq   = (const float*)d_in[3];
    const float* Wk   = (const float*)d_in[4];
    const float* Wv   = (const float*)d_in[5];
    const float* Wo   = (const float*)d_in[6];
    const float* bo   = (const float*)d_in[7];
    const float* Wg   = (const float*)d_in[8];
    const float* bg   = (const float*)d_in[9];
    float* out = (float*)d_out;

    void *pQ, *pK, *pV, *pG, *pO;
    cudaGetSymbolAddress(&pQ, g_Q);
    cudaGetSymbolAddress(&pK, g_K);
    cudaGetSymbolAddress(&pV, g_V);
    cudaGetSymbolAddress(&pG, g_G);
    cudaGetSymbolAddress(&pO, g_O);
    float* Qb = (float*)pQ; float* Kb = (float*)pK; float* Vb = (float*)pV;
    float* Gb = (float*)pG; float* Ob = (float*)pO;

    const float qscale = 0.17677669529663687f;   // 1/sqrt(32)

    dim3 gproj(CQK / GBN, NROWS / GBM);   // (2, 512)
    sgemm3<<<gproj, 256>>>(x, Wq, Qb, NROWS, CQK, CIN, 1, nullptr, qscale);
    sgemm3<<<gproj, 256>>>(x, Wk, Kb, NROWS, CQK, CIN, 0, nullptr, 1.f);
    sgemm3<<<gproj, 256>>>(x, Wv, Vb, NROWS, CQK, CIN, 0, nullptr, 1.f);
    sgemm3<<<gproj, 256>>>(x, Wg, Gb, NROWS, CQK, CIN, 2, bg, 1.f);

    detect_mask_kernel<<<1, 256>>>((const unsigned char*)mask, S_DIM * S_DIM);

    attn_kernel<<<dim3(NH, S_DIM), 256>>>(Qb, Kb, Vb, Gb, bias, mask, Ob);

    dim3 gout(CIN / GBN, NROWS / GBM);    // (1, 512)
    sgemm3<<<gout, 256>>>(Ob, Wo, out, NROWS, CIN, CQK, 3, bo, 1.f);
}